// round 2
// baseline (speedup 1.0000x reference)
#include <cuda_runtime.h>
#include <math.h>

#define NROW 131072            /* B*T*H*W */
#define BSTR 6291456           /* T*H*W*C */
#define TSTR 393216            /* H*W*C   */

__device__ float g_buf0[NROW * 96];
__device__ float g_buf1[NROW * 96];
__device__ float g_buf2[NROW * 96];
__device__ float g_buf3[NROW * 96];
__device__ float g_A [65536 * 96];
__device__ float g_Bc[65536 * 96];
__device__ float g_c64 [4096];
__device__ float g_c64T[4096];
__device__ float g_c16 [256];
__device__ float g_c16T[256];

// ---------------- cosine basis init (idempotent, runs every launch) ---------
__global__ void __launch_bounds__(256) k_cosinit() {
    int tid = threadIdx.x;
    const float PI = 3.14159265358979323846f;
    for (int i = tid; i < 4096; i += 256) {
        int n = i >> 6, xx = i & 63;
        float v = cosf((float)n * ((float)xx + 0.5f) * (PI / 64.0f)) * 0.17677669529663687f;
        if (n == 0) v *= 0.70710678118654752f;
        g_c64[n * 64 + xx] = v;
        g_c64T[xx * 64 + n] = v;
    }
    for (int i = tid; i < 256; i += 256) {
        int n = i >> 4, xx = i & 15;
        float v = cosf((float)n * ((float)xx + 0.5f) * (PI / 16.0f)) * 0.35355339059327373f;
        if (n == 0) v *= 0.70710678118654752f;
        g_c16[n * 16 + xx] = v;
        g_c16T[xx * 16 + n] = v;
    }
}

// ------------- depthwise 3x3x3 conv: x[B,C,T,H,W] -> buf0[B,C,T,H,W] --------
__global__ void __launch_bounds__(256) k_conv(const float* __restrict__ x,
                                              const float* __restrict__ wt,
                                              const float* __restrict__ bs) {
    __shared__ float xs[3 * 34 * 66];
    int htile = blockIdx.x, t = blockIdx.y, bc = blockIdx.z;
    int c = bc % 96;
    int tid = threadIdx.x;
    int h0 = htile * 32;
    for (int i = tid; i < 3 * 34 * 66; i += 256) {
        int dt = i / 2244, rem = i - dt * 2244;
        int hh = rem / 66, ww = rem - hh * 66;
        int th = t + dt - 1, gh = h0 + hh - 1, gw = ww - 1;
        float v = 0.f;
        if ((unsigned)th < 16u && (unsigned)gh < 64u && (unsigned)gw < 64u)
            v = x[(bc * 16 + th) * 4096 + gh * 64 + gw];
        xs[i] = v;
    }
    float wr[27];
#pragma unroll
    for (int j = 0; j < 27; j++) wr[j] = wt[c * 27 + j];
    float bv = bs[c];
    __syncthreads();
    int wd = tid & 63, ht = tid >> 6;
#pragma unroll
    for (int j = 0; j < 8; j++) {
        int l = ht + j * 4;
        float acc = bv;
#pragma unroll
        for (int dt = 0; dt < 3; dt++)
#pragma unroll
            for (int dh = 0; dh < 3; dh++)
#pragma unroll
                for (int dw = 0; dw < 3; dw++)
                    acc += wr[dt * 9 + dh * 3 + dw] * xs[dt * 2244 + (l + dh) * 66 + wd + dw];
        g_buf0[(bc * 16 + t) * 4096 + (h0 + l) * 64 + wd] = acc;
    }
}

// ------- linear: buf0(ch-first) -> xg=buf1[row,96], silu(z)=buf2[row,96] ----
__global__ void __launch_bounds__(256) k_linear(const float* __restrict__ lw,
                                                const float* __restrict__ lb) {
    extern __shared__ float sm[];
    float* xs = sm;               // 96*33
    float* ws = sm + 96 * 33;     // 192*97
    int tid = threadIdx.x;
    int r0 = blockIdx.x * 32;
    int b = r0 >> 16, thw0 = r0 & 65535;
    for (int i = tid; i < 96 * 32; i += 256) {
        int k = i >> 5, r = i & 31;
        xs[k * 33 + r] = g_buf0[(b * 96 + k) * 65536 + thw0 + r];
    }
    for (int i = tid; i < 192 * 96; i += 256) {
        int ccx = i / 96, kk = i - ccx * 96;
        ws[ccx * 97 + kk] = lw[i];
    }
    __syncthreads();
    int rt = tid >> 5, ct = tid & 31;
    int rr0 = rt * 4, cc0 = ct * 6;
    float acc[4][6];
#pragma unroll
    for (int i = 0; i < 4; i++)
#pragma unroll
        for (int j = 0; j < 6; j++) acc[i][j] = 0.f;
    for (int k = 0; k < 96; k++) {
        float xv[4], wv[6];
#pragma unroll
        for (int i = 0; i < 4; i++) xv[i] = xs[k * 33 + rr0 + i];
#pragma unroll
        for (int j = 0; j < 6; j++) wv[j] = ws[(cc0 + j) * 97 + k];
#pragma unroll
        for (int i = 0; i < 4; i++)
#pragma unroll
            for (int j = 0; j < 6; j++) acc[i][j] += xv[i] * wv[j];
    }
#pragma unroll
    for (int i = 0; i < 4; i++)
#pragma unroll
        for (int j = 0; j < 6; j++) {
            int ccx = cc0 + j;
            float v = acc[i][j] + lb[ccx];
            int r = r0 + rr0 + i;
            if (ccx < 96) g_buf1[r * 96 + ccx] = v;
            else g_buf2[r * 96 + ccx - 96] = v / (1.f + expf(-v));
        }
}

// ------- tau field: A, B coefficient fields [THW,96] (batch independent) ----
__global__ void __launch_bounds__(256) k_tau(const float* __restrict__ fe,
                                             const float* __restrict__ tw,
                                             const float* __restrict__ tb,
                                             const float* __restrict__ cp,
                                             const float* __restrict__ ap) {
    extern __shared__ float sm[];
    float* xs = sm;               // 96*33
    float* ws = sm + 96 * 33;     // 96*97
    int tid = threadIdx.x;
    int r0 = blockIdx.x * 32;
    for (int i = tid; i < 3072; i += 256) {
        int r = i / 96, k = i - r * 96;
        xs[k * 33 + r] = fe[r0 * 96 + i];
    }
    for (int i = tid; i < 96 * 96; i += 256) {
        int ccx = i / 96, kk = i - ccx * 96;
        ws[ccx * 97 + kk] = tw[i];
    }
    __syncthreads();
    float c0 = cp[0], al = ap[0];
    int rt = tid >> 5, ct = tid & 31;
    int rr0 = rt * 4, cc0 = ct * 3;
    float acc[4][3];
#pragma unroll
    for (int i = 0; i < 4; i++)
#pragma unroll
        for (int j = 0; j < 3; j++) acc[i][j] = 0.f;
    for (int k = 0; k < 96; k++) {
        float xv[4], wv[3];
#pragma unroll
        for (int i = 0; i < 4; i++) xv[i] = xs[k * 33 + rr0 + i];
#pragma unroll
        for (int j = 0; j < 3; j++) wv[j] = ws[(cc0 + j) * 97 + k];
#pragma unroll
        for (int i = 0; i < 4; i++)
#pragma unroll
            for (int j = 0; j < 3; j++) acc[i][j] += xv[i] * wv[j];
    }
#pragma unroll
    for (int i = 0; i < 4; i++)
#pragma unroll
        for (int j = 0; j < 3; j++) {
            int ccx = cc0 + j;
            float v = acc[i][j] + tb[ccx];
            float g = 0.5f * v * (1.f + erff(v * 0.70710678118654752f));
            float si, co;
            sincosf(c0 * g, &si, &co);
            float damp = expf(-0.5f * al * g);
            float so = si / (c0 + 1e-8f);
            int idx = (r0 + rr0 + i) * 96 + ccx;
            g_A[idx]  = damp * (co + so * al * 0.5f);
            g_Bc[idx] = damp * so;
        }
}

// ---------- generic 64-pt transform along one axis: out = M @ in ------------
__global__ void __launch_bounds__(256) k_dct64(const float* __restrict__ in,
                                               float* __restrict__ out,
                                               const float* __restrict__ M,
                                               int outer_stride, int n_inner,
                                               int axis_stride) {
    __shared__ float cs[64 * 65];
    __shared__ float xs[64 * 96];
    int tid = threadIdx.x;
    for (int i = tid; i < 4096; i += 256) cs[(i >> 6) * 65 + (i & 63)] = M[i];
    int slab = blockIdx.x;
    int outer = slab / n_inner, inner = slab - outer * n_inner;
    int base = outer * outer_stride + inner * 96;
    for (int i = tid; i < 6144; i += 256) {
        int k = i / 96, c = i - k * 96;
        xs[i] = in[base + k * axis_stride + c];
    }
    __syncthreads();
    int nt = tid >> 4, ct = tid & 15;
    int n0 = nt * 4, c0 = ct * 6;
    float acc[4][6];
#pragma unroll
    for (int i = 0; i < 4; i++)
#pragma unroll
        for (int j = 0; j < 6; j++) acc[i][j] = 0.f;
    for (int k = 0; k < 64; k++) {
        float cv[4], xv[6];
#pragma unroll
        for (int i = 0; i < 4; i++) cv[i] = cs[(n0 + i) * 65 + k];
#pragma unroll
        for (int j = 0; j < 6; j++) xv[j] = xs[k * 96 + c0 + j];
#pragma unroll
        for (int i = 0; i < 4; i++)
#pragma unroll
            for (int j = 0; j < 6; j++) acc[i][j] += cv[i] * xv[j];
    }
#pragma unroll
    for (int i = 0; i < 4; i++)
#pragma unroll
        for (int j = 0; j < 6; j++)
            out[base + (n0 + i) * axis_stride + c0 + j] = acc[i][j];
}

// ---- fused: DCT_T + v0 channel-mix + spectral combine + IDCT_T per slab ----
__global__ void __launch_bounds__(256) k_fusedT(const float* __restrict__ in,
                                                float* __restrict__ out,
                                                const float* __restrict__ vw,
                                                const float* __restrict__ vb) {
    extern __shared__ float sm[];
    float* wsm  = sm;            // 96*97 = 9312
    float* x16  = sm + 9312;     // 1536
    float* u0   = x16 + 1536;    // 1536
    float* vs   = u0 + 1536;     // 1536
    float* c16s = vs + 1536;     // 256
    float* c16t = c16s + 256;    // 256
    int tid = threadIdx.x;
    int b = blockIdx.x >> 12, hw = blockIdx.x & 4095;
    int base = b * BSTR + hw * 96;
    for (int i = tid; i < 9216; i += 256) {
        int ccx = i / 96, k = i - ccx * 96;
        wsm[ccx * 97 + k] = vw[i];
    }
    c16s[tid] = g_c16[tid];
    c16t[tid] = g_c16T[tid];
    for (int i = tid; i < 1536; i += 256) {
        int t = i / 96, c = i - t * 96;
        x16[i] = in[base + t * TSTR + c];
    }
    __syncthreads();
    int nt = tid >> 5, ct = tid & 31;
    int n0 = nt * 2, c0 = ct * 3;
    // forward DCT along T
    {
        float a[2][3] = {{0.f, 0.f, 0.f}, {0.f, 0.f, 0.f}};
        for (int t = 0; t < 16; t++) {
            float cv[2], xv[3];
#pragma unroll
            for (int i = 0; i < 2; i++) cv[i] = c16s[(n0 + i) * 16 + t];
#pragma unroll
            for (int j = 0; j < 3; j++) xv[j] = x16[t * 96 + c0 + j];
#pragma unroll
            for (int i = 0; i < 2; i++)
#pragma unroll
                for (int j = 0; j < 3; j++) a[i][j] += cv[i] * xv[j];
        }
#pragma unroll
        for (int i = 0; i < 2; i++)
#pragma unroll
            for (int j = 0; j < 3; j++) u0[(n0 + i) * 96 + c0 + j] = a[i][j];
    }
    __syncthreads();
    // v0 mix (freq domain) + spectral combine -> vs
    {
        float v[2][3] = {{0.f, 0.f, 0.f}, {0.f, 0.f, 0.f}};
        for (int k = 0; k < 96; k++) {
            float uv[2], wv[3];
#pragma unroll
            for (int i = 0; i < 2; i++) uv[i] = u0[(n0 + i) * 96 + k];
#pragma unroll
            for (int j = 0; j < 3; j++) wv[j] = wsm[(c0 + j) * 97 + k];
#pragma unroll
            for (int i = 0; i < 2; i++)
#pragma unroll
                for (int j = 0; j < 3; j++) v[i][j] += uv[i] * wv[j];
        }
        if (hw == 0 && n0 == 0) {  // DC of constant v0_b field: 256*v0_b
#pragma unroll
            for (int j = 0; j < 3; j++) v[0][j] += 256.f * vb[c0 + j];
        }
#pragma unroll
        for (int i = 0; i < 2; i++)
#pragma unroll
            for (int j = 0; j < 3; j++) {
                int gi = ((n0 + i) * 4096 + hw) * 96 + c0 + j;
                int li = (n0 + i) * 96 + c0 + j;
                vs[li] = g_A[gi] * u0[li] + g_Bc[gi] * v[i][j];
            }
    }
    __syncthreads();
    // inverse DCT along T
    {
        float y[2][3] = {{0.f, 0.f, 0.f}, {0.f, 0.f, 0.f}};
        for (int n = 0; n < 16; n++) {
            float cv[2], sv[3];
#pragma unroll
            for (int i = 0; i < 2; i++) cv[i] = c16t[(n0 + i) * 16 + n];
#pragma unroll
            for (int j = 0; j < 3; j++) sv[j] = vs[n * 96 + c0 + j];
#pragma unroll
            for (int i = 0; i < 2; i++)
#pragma unroll
                for (int j = 0; j < 3; j++) y[i][j] += cv[i] * sv[j];
        }
#pragma unroll
        for (int i = 0; i < 2; i++)
#pragma unroll
            for (int j = 0; j < 3; j++)
                out[base + (n0 + i) * TSTR + c0 + j] = y[i][j];
    }
}

// ---- final: LayerNorm + gate + out GEMM + transpose to [B,C,T,H,W] ---------
__global__ void __launch_bounds__(256) k_final(const float* __restrict__ lg,
                                               const float* __restrict__ lbt,
                                               const float* __restrict__ ow,
                                               const float* __restrict__ ob,
                                               float* __restrict__ outp) {
    extern __shared__ float sm[];
    float* xs = sm;              // 32*97 = 3104
    float* ws = sm + 3104;       // 96*97 = 9312
    float* os = ws + 9312;       // 96*33 = 3168
    int tid = threadIdx.x;
    int r0 = blockIdx.x * 32;
    int b = r0 >> 16, thw0 = r0 & 65535;
    for (int i = tid; i < 3072; i += 256) {
        int r = i / 96, c = i - r * 96;
        xs[r * 97 + c] = g_buf3[r0 * 96 + i];
    }
    for (int i = tid; i < 9216; i += 256) {
        int ccx = i / 96, k = i - ccx * 96;
        ws[ccx * 97 + k] = ow[i];
    }
    __syncthreads();
    int wp = tid >> 5, lane = tid & 31;
#pragma unroll
    for (int rr = 0; rr < 4; rr++) {
        int r = wp * 4 + rr;
        float x0 = xs[r * 97 + lane], x1 = xs[r * 97 + lane + 32], x2 = xs[r * 97 + lane + 64];
        float s = x0 + x1 + x2, q = x0 * x0 + x1 * x1 + x2 * x2;
#pragma unroll
        for (int o = 16; o > 0; o >>= 1) {
            s += __shfl_xor_sync(0xffffffffu, s, o);
            q += __shfl_xor_sync(0xffffffffu, q, o);
        }
        float mean = s * (1.f / 96.f);
        float var = q * (1.f / 96.f) - mean * mean;
        float rstd = rsqrtf(var + 1e-5f);
        int gr = (r0 + r) * 96;
        xs[r * 97 + lane]      = ((x0 - mean) * rstd * lg[lane]      + lbt[lane])      * g_buf2[gr + lane];
        xs[r * 97 + lane + 32] = ((x1 - mean) * rstd * lg[lane + 32] + lbt[lane + 32]) * g_buf2[gr + lane + 32];
        xs[r * 97 + lane + 64] = ((x2 - mean) * rstd * lg[lane + 64] + lbt[lane + 64]) * g_buf2[gr + lane + 64];
    }
    __syncthreads();
    int rt = tid >> 5, ct = tid & 31;
    int rr0 = rt * 4, cc0 = ct * 3;
    float acc[4][3];
#pragma unroll
    for (int i = 0; i < 4; i++)
#pragma unroll
        for (int j = 0; j < 3; j++) acc[i][j] = 0.f;
    for (int k = 0; k < 96; k++) {
        float xv[4], wv[3];
#pragma unroll
        for (int i = 0; i < 4; i++) xv[i] = xs[(rr0 + i) * 97 + k];
#pragma unroll
        for (int j = 0; j < 3; j++) wv[j] = ws[(cc0 + j) * 97 + k];
#pragma unroll
        for (int i = 0; i < 4; i++)
#pragma unroll
            for (int j = 0; j < 3; j++) acc[i][j] += xv[i] * wv[j];
    }
#pragma unroll
    for (int i = 0; i < 4; i++)
#pragma unroll
        for (int j = 0; j < 3; j++)
            os[(cc0 + j) * 33 + rr0 + i] = acc[i][j] + ob[cc0 + j];
    __syncthreads();
    for (int i = tid; i < 3072; i += 256) {
        int ccx = i >> 5, rr = i & 31;
        outp[b * BSTR + ccx * 65536 + thw0 + rr] = os[ccx * 33 + rr];
    }
}

extern "C" void kernel_launch(void* const* d_in, const int* in_sizes, int n_in,
                              void* d_out, int out_size) {
    const float* x   = (const float*)d_in[0];
    const float* fe  = (const float*)d_in[1];
    const float* dww = (const float*)d_in[2];
    const float* dwb = (const float*)d_in[3];
    const float* lw  = (const float*)d_in[4];
    const float* lb  = (const float*)d_in[5];
    const float* vw  = (const float*)d_in[6];
    const float* vb  = (const float*)d_in[7];
    const float* tw  = (const float*)d_in[8];
    const float* tb  = (const float*)d_in[9];
    const float* cc  = (const float*)d_in[10];
    const float* al  = (const float*)d_in[11];
    const float* lg  = (const float*)d_in[12];
    const float* lbt = (const float*)d_in[13];
    const float* ow  = (const float*)d_in[14];
    const float* ob  = (const float*)d_in[15];
    float* outp = (float*)d_out;

    size_t smLin = (size_t)(96 * 33 + 192 * 97) * 4;   // 87168
    size_t smTau = (size_t)(96 * 33 + 96 * 97) * 4;    // 49920
    size_t smFus = (size_t)(9312 + 3 * 1536 + 512) * 4;// 57728
    size_t smFin = (size_t)(3104 + 9312 + 3168) * 4;   // 62336
    cudaFuncSetAttribute(k_linear, cudaFuncAttributeMaxDynamicSharedMemorySize, (int)smLin);
    cudaFuncSetAttribute(k_tau,    cudaFuncAttributeMaxDynamicSharedMemorySize, (int)smTau);
    cudaFuncSetAttribute(k_fusedT, cudaFuncAttributeMaxDynamicSharedMemorySize, (int)smFus);
    cudaFuncSetAttribute(k_final,  cudaFuncAttributeMaxDynamicSharedMemorySize, (int)smFin);

    float *b0, *b1, *b3, *c64, *c64T;
    cudaGetSymbolAddress((void**)&b0, g_buf0);
    cudaGetSymbolAddress((void**)&b1, g_buf1);
    cudaGetSymbolAddress((void**)&b3, g_buf3);
    cudaGetSymbolAddress((void**)&c64, g_c64);
    cudaGetSymbolAddress((void**)&c64T, g_c64T);

    k_cosinit<<<1, 256>>>();
    k_conv<<<dim3(2, 16, 192), 256>>>(x, dww, dwb);
    k_linear<<<4096, 256, smLin>>>(lw, lb);
    k_tau<<<2048, 256, smTau>>>(fe, tw, tb, cc, al);
    k_dct64<<<2048, 256>>>(b1, b3, c64, 6144, 1, 96);        // DCT along W
    k_dct64<<<2048, 256>>>(b3, b0, c64, 393216, 64, 6144);   // DCT along H
    k_fusedT<<<8192, 256, smFus>>>(b0, b3, vw, vb);          // DCT_T+mix+IDCT_T
    k_dct64<<<2048, 256>>>(b3, b1, c64T, 393216, 64, 6144);  // IDCT along H
    k_dct64<<<2048, 256>>>(b1, b3, c64T, 6144, 1, 96);       // IDCT along W
    k_final<<<4096, 256, smFin>>>(lg, lbt, ow, ob, outp);
}

// round 3
// speedup vs baseline: 1.0785x; 1.0785x over previous
#include <cuda_runtime.h>
#include <math.h>

#define NROW 131072            /* B*T*H*W */
#define BSTR 6291456           /* T*H*W*C */
#define TSTR 393216            /* H*W*C   */

__device__ float g_buf0[NROW * 96];
__device__ float g_buf1[NROW * 96];
__device__ float g_buf2[NROW * 96];
__device__ float g_buf3[NROW * 96];
__device__ float g_A [65536 * 96];
__device__ float g_Bc[65536 * 96];
__device__ float g_c64 [4096];
__device__ float g_c64T[4096];
__device__ float g_c16 [256];
__device__ float g_c16T[256];
__device__ float g_lwT[96 * 192];
__device__ float g_twT[96 * 96];
__device__ float g_vwT[96 * 96];
__device__ float g_owT[96 * 96];

// packed dual-fp32 FMA (FFMA2) — 2 FMAs per issue, exact fp32 rounding
__device__ __forceinline__ float2 ffma2(float2 a, float2 b, float2 c) {
    float2 d;
    asm("fma.rn.f32x2 %0, %1, %2, %3;"
        : "=l"(reinterpret_cast<unsigned long long&>(d))
        : "l"(reinterpret_cast<unsigned long long&>(a)),
          "l"(reinterpret_cast<unsigned long long&>(b)),
          "l"(reinterpret_cast<unsigned long long&>(c)));
    return d;
}

// ---------------- cosine basis init (idempotent) -----------------------------
__global__ void __launch_bounds__(256) k_cosinit() {
    int tid = threadIdx.x;
    const float PI = 3.14159265358979323846f;
    for (int i = tid; i < 4096; i += 256) {
        int n = i >> 6, xx = i & 63;
        float v = cosf((float)n * ((float)xx + 0.5f) * (PI / 64.0f)) * 0.17677669529663687f;
        if (n == 0) v *= 0.70710678118654752f;
        g_c64[n * 64 + xx] = v;
        g_c64T[xx * 64 + n] = v;
    }
    for (int i = tid; i < 256; i += 256) {
        int n = i >> 4, xx = i & 15;
        float v = cosf((float)n * ((float)xx + 0.5f) * (PI / 16.0f)) * 0.35355339059327373f;
        if (n == 0) v *= 0.70710678118654752f;
        g_c16[n * 16 + xx] = v;
        g_c16T[xx * 16 + n] = v;
    }
}

// ---------------- weight pre-transpose to k-major ----------------------------
__global__ void __launch_bounds__(256) k_prepw(const float* __restrict__ lw,
                                               const float* __restrict__ tw,
                                               const float* __restrict__ vw,
                                               const float* __restrict__ ow) {
    int i = blockIdx.x * 256 + threadIdx.x;
    if (i < 18432) {
        int cc = i / 96, k = i - cc * 96;
        g_lwT[k * 192 + cc] = lw[i];
    } else if (i < 27648) {
        int j = i - 18432; int cc = j / 96, k = j - cc * 96;
        g_twT[k * 96 + cc] = tw[j];
    } else if (i < 36864) {
        int j = i - 27648; int cc = j / 96, k = j - cc * 96;
        g_vwT[k * 96 + cc] = vw[j];
    } else if (i < 46080) {
        int j = i - 36864; int cc = j / 96, k = j - cc * 96;
        g_owT[k * 96 + cc] = ow[j];
    }
}

// ------------- depthwise 3x3x3 conv: x[B,C,T,H,W] -> buf0[B,C,T,H,W] --------
__global__ void __launch_bounds__(256) k_conv(const float* __restrict__ x,
                                              const float* __restrict__ wt,
                                              const float* __restrict__ bs) {
    __shared__ float xs[3 * 34 * 66];
    int htile = blockIdx.x, t = blockIdx.y, bc = blockIdx.z;
    int c = bc % 96;
    int tid = threadIdx.x;
    int h0 = htile * 32;
    for (int i = tid; i < 3 * 34 * 66; i += 256) {
        int dt = i / 2244, rem = i - dt * 2244;
        int hh = rem / 66, ww = rem - hh * 66;
        int th = t + dt - 1, gh = h0 + hh - 1, gw = ww - 1;
        float v = 0.f;
        if ((unsigned)th < 16u && (unsigned)gh < 64u && (unsigned)gw < 64u)
            v = x[(bc * 16 + th) * 4096 + gh * 64 + gw];
        xs[i] = v;
    }
    float wr[27];
#pragma unroll
    for (int j = 0; j < 27; j++) wr[j] = wt[c * 27 + j];
    float bv = bs[c];
    __syncthreads();
    int wd = tid & 63, ht = tid >> 6;
#pragma unroll
    for (int j = 0; j < 8; j++) {
        int l = ht + j * 4;
        float acc = bv;
#pragma unroll
        for (int dt = 0; dt < 3; dt++)
#pragma unroll
            for (int dh = 0; dh < 3; dh++)
#pragma unroll
                for (int dw = 0; dw < 3; dw++)
                    acc += wr[dt * 9 + dh * 3 + dw] * xs[dt * 2244 + (l + dh) * 66 + wd + dw];
        g_buf0[(bc * 16 + t) * 4096 + (h0 + l) * 64 + wd] = acc;
    }
}

// ------- linear: buf0(ch-first) -> xg=buf1[row,96], silu(z)=buf2[row,96] ----
__global__ void __launch_bounds__(256) k_linear(const float* __restrict__ lb) {
    extern __shared__ float sm[];
    float* xs = sm;               // 96*65 = 6240
    float* ws = sm + 6240;        // 96*194 = 18624 (k-major)
    int tid = threadIdx.x;
    int r0 = blockIdx.x * 64;
    int b = r0 >> 16, thw0 = r0 & 65535;
    for (int i = tid; i < 96 * 64; i += 256) {
        int k = i >> 6, r = i & 63;
        xs[k * 65 + r] = g_buf0[(b * 96 + k) * 65536 + thw0 + r];
    }
    for (int i = tid; i < 96 * 192; i += 256) {
        int k = i / 192, cc = i - k * 192;
        ws[k * 194 + cc] = g_lwT[i];
    }
    __syncthreads();
    int rt = tid >> 4, ct = tid & 15;
    int rr0 = rt * 4, cc0 = ct * 12;
    float2 acc[4][6];
#pragma unroll
    for (int i = 0; i < 4; i++)
#pragma unroll
        for (int j = 0; j < 6; j++) acc[i][j] = make_float2(0.f, 0.f);
    for (int k = 0; k < 96; k++) {
        float2 xv[4];
#pragma unroll
        for (int i = 0; i < 4; i++) {
            float xv1 = xs[k * 65 + rr0 + i];
            xv[i] = make_float2(xv1, xv1);
        }
        const float2* wp = (const float2*)&ws[k * 194 + cc0];
        float2 wv[6];
#pragma unroll
        for (int j = 0; j < 6; j++) wv[j] = wp[j];
#pragma unroll
        for (int i = 0; i < 4; i++)
#pragma unroll
            for (int j = 0; j < 6; j++) acc[i][j] = ffma2(xv[i], wv[j], acc[i][j]);
    }
#pragma unroll
    for (int i = 0; i < 4; i++) {
        int r = r0 + rr0 + i;
#pragma unroll
        for (int j = 0; j < 6; j++) {
            int cc = cc0 + 2 * j;
            float2 v = acc[i][j];
            v.x += lb[cc]; v.y += lb[cc + 1];
            if (cc < 96) {
                *(float2*)&g_buf1[r * 96 + cc] = v;
            } else {
                float2 o;
                o.x = v.x / (1.f + expf(-v.x));
                o.y = v.y / (1.f + expf(-v.y));
                *(float2*)&g_buf2[r * 96 + cc - 96] = o;
            }
        }
    }
}

// ------- tau field: A, B coefficient fields [THW,96] (batch independent) ----
__global__ void __launch_bounds__(256) k_tau(const float* __restrict__ fe,
                                             const float* __restrict__ tb,
                                             const float* __restrict__ cp,
                                             const float* __restrict__ ap) {
    extern __shared__ float sm[];
    float* xs = sm;               // 96*65 = 6240
    float* ws = sm + 6240;        // 96*98 = 9408
    int tid = threadIdx.x;
    int r0 = blockIdx.x * 64;
    for (int i = tid; i < 96 * 64; i += 256) {
        int r = i / 96, k = i - r * 96;
        xs[k * 65 + r] = fe[r0 * 96 + i];
    }
    for (int i = tid; i < 96 * 96; i += 256) {
        int k = i / 96, cc = i - k * 96;
        ws[k * 98 + cc] = g_twT[i];
    }
    __syncthreads();
    float c0 = cp[0], al = ap[0];
    int rt = tid >> 4, ct = tid & 15;
    int rr0 = rt * 4, cc0 = ct * 6;
    float2 acc[4][3];
#pragma unroll
    for (int i = 0; i < 4; i++)
#pragma unroll
        for (int j = 0; j < 3; j++) acc[i][j] = make_float2(0.f, 0.f);
    for (int k = 0; k < 96; k++) {
        float2 xv[4];
#pragma unroll
        for (int i = 0; i < 4; i++) {
            float x1 = xs[k * 65 + rr0 + i];
            xv[i] = make_float2(x1, x1);
        }
        const float2* wp = (const float2*)&ws[k * 98 + cc0];
        float2 wv[3];
#pragma unroll
        for (int j = 0; j < 3; j++) wv[j] = wp[j];
#pragma unroll
        for (int i = 0; i < 4; i++)
#pragma unroll
            for (int j = 0; j < 3; j++) acc[i][j] = ffma2(xv[i], wv[j], acc[i][j]);
    }
#pragma unroll
    for (int i = 0; i < 4; i++) {
#pragma unroll
        for (int j = 0; j < 3; j++) {
            int cc = cc0 + 2 * j;
            float2 v = acc[i][j];
            v.x += tb[cc]; v.y += tb[cc + 1];
            float2 Av, Bv;
            {
                float g = 0.5f * v.x * (1.f + erff(v.x * 0.70710678118654752f));
                float si, co; sincosf(c0 * g, &si, &co);
                float damp = expf(-0.5f * al * g);
                float so = si / (c0 + 1e-8f);
                Av.x = damp * (co + so * al * 0.5f); Bv.x = damp * so;
            }
            {
                float g = 0.5f * v.y * (1.f + erff(v.y * 0.70710678118654752f));
                float si, co; sincosf(c0 * g, &si, &co);
                float damp = expf(-0.5f * al * g);
                float so = si / (c0 + 1e-8f);
                Av.y = damp * (co + so * al * 0.5f); Bv.y = damp * so;
            }
            int idx = (r0 + rr0 + i) * 96 + cc;
            *(float2*)&g_A[idx]  = Av;
            *(float2*)&g_Bc[idx] = Bv;
        }
    }
}

// ---------- generic 64-pt transform along one axis: out = M @ in ------------
__global__ void __launch_bounds__(256) k_dct64(const float* __restrict__ in,
                                               float* __restrict__ out,
                                               const float* __restrict__ M,
                                               int outer_stride, int n_inner,
                                               int axis_stride) {
    __shared__ float cs[64 * 65];
    __shared__ float xs[64 * 98];
    int tid = threadIdx.x;
    for (int i = tid; i < 4096; i += 256) cs[(i >> 6) * 65 + (i & 63)] = M[i];
    int slab = blockIdx.x;
    int outer = slab / n_inner, inner = slab - outer * n_inner;
    int base = outer * outer_stride + inner * 96;
    for (int i = tid; i < 3072; i += 256) {
        int k = i / 48, c2 = i - k * 48;
        float2 v = *(const float2*)&in[base + k * axis_stride + c2 * 2];
        *(float2*)&xs[k * 98 + c2 * 2] = v;
    }
    __syncthreads();
    int nt = tid >> 4, ct = tid & 15;
    int n0 = nt * 4, c0 = ct * 6;
    float2 acc[4][3];
#pragma unroll
    for (int i = 0; i < 4; i++)
#pragma unroll
        for (int j = 0; j < 3; j++) acc[i][j] = make_float2(0.f, 0.f);
    for (int k = 0; k < 64; k++) {
        float2 cv[4];
#pragma unroll
        for (int i = 0; i < 4; i++) {
            float c1 = cs[(n0 + i) * 65 + k];
            cv[i] = make_float2(c1, c1);
        }
        const float2* xp = (const float2*)&xs[k * 98 + c0];
        float2 xv[3];
#pragma unroll
        for (int j = 0; j < 3; j++) xv[j] = xp[j];
#pragma unroll
        for (int i = 0; i < 4; i++)
#pragma unroll
            for (int j = 0; j < 3; j++) acc[i][j] = ffma2(cv[i], xv[j], acc[i][j]);
    }
#pragma unroll
    for (int i = 0; i < 4; i++)
#pragma unroll
        for (int j = 0; j < 3; j++)
            *(float2*)&out[base + (n0 + i) * axis_stride + c0 + 2 * j] = acc[i][j];
}

// ---- fused: DCT_T + v0 channel-mix + spectral combine + IDCT_T per slab ----
__global__ void __launch_bounds__(256) k_fusedT(const float* __restrict__ in,
                                                float* __restrict__ out,
                                                const float* __restrict__ vb) {
    extern __shared__ float sm[];
    float* wsm  = sm;            // 96*98 = 9408
    float* x16  = sm + 9408;     // 1536
    float* u0   = x16 + 1536;    // 1536
    float* vs   = u0 + 1536;     // 1536
    float* c16s = vs + 1536;     // 256
    float* c16t = c16s + 256;    // 256
    int tid = threadIdx.x;
    int b = blockIdx.x >> 12, hw = blockIdx.x & 4095;
    int base = b * BSTR + hw * 96;
    for (int i = tid; i < 9216; i += 256) {
        int k = i / 96, cc = i - k * 96;
        wsm[k * 98 + cc] = g_vwT[i];
    }
    c16s[tid] = g_c16[tid];
    c16t[tid] = g_c16T[tid];
    for (int i = tid; i < 1536; i += 256) {
        int t = i / 96, c = i - t * 96;
        x16[i] = in[base + t * TSTR + c];
    }
    __syncthreads();
    int nt = tid >> 4, ct = tid & 15;
    int c0 = ct * 6;
    // forward DCT along T (thread owns frequency row n = nt, 6 channels)
    {
        float2 a[3] = {make_float2(0,0), make_float2(0,0), make_float2(0,0)};
        for (int t = 0; t < 16; t++) {
            float c1 = c16s[nt * 16 + t];
            float2 cv = make_float2(c1, c1);
            const float2* xp = (const float2*)&x16[t * 96 + c0];
#pragma unroll
            for (int j = 0; j < 3; j++) a[j] = ffma2(cv, xp[j], a[j]);
        }
#pragma unroll
        for (int j = 0; j < 3; j++) *(float2*)&u0[nt * 96 + c0 + 2 * j] = a[j];
    }
    __syncthreads();
    // v0 mix (freq domain) + spectral combine -> vs
    {
        float2 v[3] = {make_float2(0,0), make_float2(0,0), make_float2(0,0)};
        for (int k = 0; k < 96; k++) {
            float u1 = u0[nt * 96 + k];
            float2 uv = make_float2(u1, u1);
            const float2* wp = (const float2*)&wsm[k * 98 + c0];
#pragma unroll
            for (int j = 0; j < 3; j++) v[j] = ffma2(uv, wp[j], v[j]);
        }
        if (hw == 0 && nt == 0) {  // DC of constant v0_b field: 256*v0_b
#pragma unroll
            for (int j = 0; j < 3; j++) {
                v[j].x += 256.f * vb[c0 + 2 * j];
                v[j].y += 256.f * vb[c0 + 2 * j + 1];
            }
        }
#pragma unroll
        for (int j = 0; j < 3; j++) {
            int cc = c0 + 2 * j;
            int gi = (nt * 4096 + hw) * 96 + cc;
            float2 Av = *(const float2*)&g_A[gi];
            float2 Bv = *(const float2*)&g_Bc[gi];
            float2 uu = *(const float2*)&u0[nt * 96 + cc];
            float2 r;
            r.x = Av.x * uu.x + Bv.x * v[j].x;
            r.y = Av.y * uu.y + Bv.y * v[j].y;
            *(float2*)&vs[nt * 96 + cc] = r;
        }
    }
    __syncthreads();
    // inverse DCT along T (thread owns time index t = nt)
    {
        float2 y[3] = {make_float2(0,0), make_float2(0,0), make_float2(0,0)};
        for (int n = 0; n < 16; n++) {
            float c1 = c16t[nt * 16 + n];
            float2 cv = make_float2(c1, c1);
            const float2* sp = (const float2*)&vs[n * 96 + c0];
#pragma unroll
            for (int j = 0; j < 3; j++) y[j] = ffma2(cv, sp[j], y[j]);
        }
#pragma unroll
        for (int j = 0; j < 3; j++)
            *(float2*)&out[base + nt * TSTR + c0 + 2 * j] = y[j];
    }
}

// ---- final: LayerNorm + gate + out GEMM + transpose to [B,C,T,H,W] ---------
__global__ void __launch_bounds__(256) k_final(const float* __restrict__ lg,
                                               const float* __restrict__ lbt,
                                               const float* __restrict__ ob,
                                               float* __restrict__ outp) {
    extern __shared__ float sm[];
    float* xs = sm;              // 64*97 = 6208
    float* ws = sm + 6208;       // 96*98 = 9408
    float* os = ws + 9408;       // 96*65 = 6240
    int tid = threadIdx.x;
    int r0 = blockIdx.x * 64;
    int b = r0 >> 16, thw0 = r0 & 65535;
    for (int i = tid; i < 6144; i += 256) {
        int r = i / 96, c = i - r * 96;
        xs[r * 97 + c] = g_buf3[r0 * 96 + i];
    }
    for (int i = tid; i < 9216; i += 256) {
        int k = i / 96, cc = i - k * 96;
        ws[k * 98 + cc] = g_owT[i];
    }
    __syncthreads();
    int wp = tid >> 5, lane = tid & 31;
#pragma unroll
    for (int rr = 0; rr < 8; rr++) {
        int r = wp * 8 + rr;
        float x0 = xs[r * 97 + lane], x1 = xs[r * 97 + lane + 32], x2 = xs[r * 97 + lane + 64];
        float s = x0 + x1 + x2, q = x0 * x0 + x1 * x1 + x2 * x2;
#pragma unroll
        for (int o = 16; o > 0; o >>= 1) {
            s += __shfl_xor_sync(0xffffffffu, s, o);
            q += __shfl_xor_sync(0xffffffffu, q, o);
        }
        float mean = s * (1.f / 96.f);
        float var = q * (1.f / 96.f) - mean * mean;
        float rstd = rsqrtf(var + 1e-5f);
        int gr = (r0 + r) * 96;
        xs[r * 97 + lane]      = ((x0 - mean) * rstd * lg[lane]      + lbt[lane])      * g_buf2[gr + lane];
        xs[r * 97 + lane + 32] = ((x1 - mean) * rstd * lg[lane + 32] + lbt[lane + 32]) * g_buf2[gr + lane + 32];
        xs[r * 97 + lane + 64] = ((x2 - mean) * rstd * lg[lane + 64] + lbt[lane + 64]) * g_buf2[gr + lane + 64];
    }
    __syncthreads();
    int rt = tid >> 4, ct = tid & 15;
    int rr0 = rt * 4, cc0 = ct * 6;
    float2 acc[4][3];
#pragma unroll
    for (int i = 0; i < 4; i++)
#pragma unroll
        for (int j = 0; j < 3; j++) acc[i][j] = make_float2(0.f, 0.f);
    for (int k = 0; k < 96; k++) {
        float2 xv[4];
#pragma unroll
        for (int i = 0; i < 4; i++) {
            float x1 = xs[(rr0 + i) * 97 + k];
            xv[i] = make_float2(x1, x1);
        }
        const float2* wpp = (const float2*)&ws[k * 98 + cc0];
        float2 wv[3];
#pragma unroll
        for (int j = 0; j < 3; j++) wv[j] = wpp[j];
#pragma unroll
        for (int i = 0; i < 4; i++)
#pragma unroll
            for (int j = 0; j < 3; j++) acc[i][j] = ffma2(xv[i], wv[j], acc[i][j]);
    }
#pragma unroll
    for (int i = 0; i < 4; i++)
#pragma unroll
        for (int j = 0; j < 3; j++) {
            int cc = cc0 + 2 * j;
            os[cc * 65 + rr0 + i]       = acc[i][j].x + ob[cc];
            os[(cc + 1) * 65 + rr0 + i] = acc[i][j].y + ob[cc + 1];
        }
    __syncthreads();
    for (int i = tid; i < 6144; i += 256) {
        int cc = i >> 6, rr = i & 63;
        outp[b * BSTR + cc * 65536 + thw0 + rr] = os[cc * 65 + rr];
    }
}

extern "C" void kernel_launch(void* const* d_in, const int* in_sizes, int n_in,
                              void* d_out, int out_size) {
    const float* x   = (const float*)d_in[0];
    const float* fe  = (const float*)d_in[1];
    const float* dww = (const float*)d_in[2];
    const float* dwb = (const float*)d_in[3];
    const float* lw  = (const float*)d_in[4];
    const float* lb  = (const float*)d_in[5];
    const float* vw  = (const float*)d_in[6];
    const float* vb  = (const float*)d_in[7];
    const float* tw  = (const float*)d_in[8];
    const float* tb  = (const float*)d_in[9];
    const float* cc  = (const float*)d_in[10];
    const float* al  = (const float*)d_in[11];
    const float* lg  = (const float*)d_in[12];
    const float* lbt = (const float*)d_in[13];
    const float* ow  = (const float*)d_in[14];
    const float* ob  = (const float*)d_in[15];
    float* outp = (float*)d_out;

    size_t smLin = (size_t)(6240 + 18624) * 4;           // 99456
    size_t smTau = (size_t)(6240 + 9408) * 4;            // 62592
    size_t smFus = (size_t)(9408 + 3 * 1536 + 512) * 4;  // 58112
    size_t smFin = (size_t)(6208 + 9408 + 6240) * 4;     // 87424
    cudaFuncSetAttribute(k_linear, cudaFuncAttributeMaxDynamicSharedMemorySize, (int)smLin);
    cudaFuncSetAttribute(k_tau,    cudaFuncAttributeMaxDynamicSharedMemorySize, (int)smTau);
    cudaFuncSetAttribute(k_fusedT, cudaFuncAttributeMaxDynamicSharedMemorySize, (int)smFus);
    cudaFuncSetAttribute(k_final,  cudaFuncAttributeMaxDynamicSharedMemorySize, (int)smFin);

    float *b0, *b1, *b3, *c64, *c64T;
    cudaGetSymbolAddress((void**)&b0, g_buf0);
    cudaGetSymbolAddress((void**)&b1, g_buf1);
    cudaGetSymbolAddress((void**)&b3, g_buf3);
    cudaGetSymbolAddress((void**)&c64, g_c64);
    cudaGetSymbolAddress((void**)&c64T, g_c64T);

    k_cosinit<<<1, 256>>>();
    k_prepw<<<180, 256>>>(lw, tw, vw, ow);
    k_conv<<<dim3(2, 16, 192), 256>>>(x, dww, dwb);
    k_linear<<<2048, 256, smLin>>>(lb);
    k_tau<<<1024, 256, smTau>>>(fe, tb, cc, al);
    k_dct64<<<2048, 256>>>(b1, b3, c64, 6144, 1, 96);        // DCT along W
    k_dct64<<<2048, 256>>>(b3, b0, c64, 393216, 64, 6144);   // DCT along H
    k_fusedT<<<8192, 256, smFus>>>(b0, b3, vb);              // DCT_T+mix+IDCT_T
    k_dct64<<<2048, 256>>>(b3, b1, c64T, 393216, 64, 6144);  // IDCT along H
    k_dct64<<<2048, 256>>>(b1, b3, c64T, 6144, 1, 96);       // IDCT along W
    k_final<<<2048, 256, smFin>>>(lg, lbt, ob, outp);
}

// round 4
// speedup vs baseline: 1.2140x; 1.1256x over previous
#include <cuda_runtime.h>
#include <math.h>

#define NROW 131072            /* B*T*H*W */
#define BSTR 6291456           /* T*H*W*C */
#define TSTR 393216            /* H*W*C   */

__device__ float g_buf0[NROW * 96];
__device__ float g_buf1[NROW * 96];
__device__ float g_buf2[NROW * 96];
__device__ float g_buf3[NROW * 96];
__device__ float g_A [65536 * 96];
__device__ float g_Bc[65536 * 96];
__device__ float g_c64 [4096];
__device__ float g_c64T[4096];
__device__ float g_c16 [256];
__device__ float g_c16T[256];
__device__ float g_lwT[96 * 192];
__device__ float g_twT[96 * 96];
__device__ float g_vwT[96 * 96];
__device__ float g_owT[96 * 96];

// packed dual-fp32 FMA (FFMA2) — 2 FMAs per issue slot, exact fp32 rounding
__device__ __forceinline__ float2 ffma2(float2 a, float2 b, float2 c) {
    float2 d;
    asm("fma.rn.f32x2 %0, %1, %2, %3;"
        : "=l"(reinterpret_cast<unsigned long long&>(d))
        : "l"(reinterpret_cast<unsigned long long&>(a)),
          "l"(reinterpret_cast<unsigned long long&>(b)),
          "l"(reinterpret_cast<unsigned long long&>(c)));
    return d;
}

// ---------------- cosine basis init (idempotent) -----------------------------
__global__ void __launch_bounds__(256) k_cosinit() {
    int tid = threadIdx.x;
    const float PI = 3.14159265358979323846f;
    for (int i = tid; i < 4096; i += 256) {
        int n = i >> 6, xx = i & 63;
        float v = cosf((float)n * ((float)xx + 0.5f) * (PI / 64.0f)) * 0.17677669529663687f;
        if (n == 0) v *= 0.70710678118654752f;
        g_c64[n * 64 + xx] = v;
        g_c64T[xx * 64 + n] = v;
    }
    for (int i = tid; i < 256; i += 256) {
        int n = i >> 4, xx = i & 15;
        float v = cosf((float)n * ((float)xx + 0.5f) * (PI / 16.0f)) * 0.35355339059327373f;
        if (n == 0) v *= 0.70710678118654752f;
        g_c16[n * 16 + xx] = v;
        g_c16T[xx * 16 + n] = v;
    }
}

// ---------------- weight pre-transpose to k-major ----------------------------
__global__ void __launch_bounds__(256) k_prepw(const float* __restrict__ lw,
                                               const float* __restrict__ tw,
                                               const float* __restrict__ vw,
                                               const float* __restrict__ ow) {
    int i = blockIdx.x * 256 + threadIdx.x;
    if (i < 18432) {
        int cc = i / 96, k = i - cc * 96;
        g_lwT[k * 192 + cc] = lw[i];
    } else if (i < 27648) {
        int j = i - 18432; int cc = j / 96, k = j - cc * 96;
        g_twT[k * 96 + cc] = tw[j];
    } else if (i < 36864) {
        int j = i - 27648; int cc = j / 96, k = j - cc * 96;
        g_vwT[k * 96 + cc] = vw[j];
    } else if (i < 46080) {
        int j = i - 36864; int cc = j / 96, k = j - cc * 96;
        g_owT[k * 96 + cc] = ow[j];
    }
}

// ------------- depthwise 3x3x3 conv: x[B,C,T,H,W] -> buf0[B,C,T,H,W] --------
__global__ void __launch_bounds__(256) k_conv(const float* __restrict__ x,
                                              const float* __restrict__ wt,
                                              const float* __restrict__ bs) {
    __shared__ float xs[3 * 34 * 66];
    int htile = blockIdx.x, t = blockIdx.y, bc = blockIdx.z;
    int c = bc % 96;
    int tid = threadIdx.x;
    int h0 = htile * 32;
    for (int i = tid; i < 3 * 34 * 66; i += 256) {
        int dt = i / 2244, rem = i - dt * 2244;
        int hh = rem / 66, ww = rem - hh * 66;
        int th = t + dt - 1, gh = h0 + hh - 1, gw = ww - 1;
        float v = 0.f;
        if ((unsigned)th < 16u && (unsigned)gh < 64u && (unsigned)gw < 64u)
            v = x[(bc * 16 + th) * 4096 + gh * 64 + gw];
        xs[i] = v;
    }
    float wr[27];
#pragma unroll
    for (int j = 0; j < 27; j++) wr[j] = wt[c * 27 + j];
    float bv = bs[c];
    __syncthreads();
    int wd = tid & 63, ht = tid >> 6;
#pragma unroll
    for (int j = 0; j < 8; j++) {
        int l = ht + j * 4;
        float acc = bv;
#pragma unroll
        for (int dt = 0; dt < 3; dt++)
#pragma unroll
            for (int dh = 0; dh < 3; dh++)
#pragma unroll
                for (int dw = 0; dw < 3; dw++)
                    acc += wr[dt * 9 + dh * 3 + dw] * xs[dt * 2244 + (l + dh) * 66 + wd + dw];
        g_buf0[(bc * 16 + t) * 4096 + (h0 + l) * 64 + wd] = acc;
    }
}

// ---- linear(xg half) + bias + DCT along W: buf0 -> buf1 (W in freq space) --
__global__ void __launch_bounds__(256) k_linxg(const float* __restrict__ lb) {
    extern __shared__ float sm[];
    float* xs = sm;              // 96*66 = 6336 (k-major input; reused as yx[64*98])
    float* ws = sm + 6336;       // 96*98 = 9408
    float* cs = ws + 9408;       // 64*65 = 4160
    int tid = threadIdx.x;
    int r0 = blockIdx.x * 64;
    int b = r0 >> 16, thw0 = r0 & 65535;
    for (int i = tid; i < 6144; i += 256) {
        int k = i >> 6, r = i & 63;
        xs[k * 66 + r] = g_buf0[(b * 96 + k) * 65536 + thw0 + r];
    }
    for (int i = tid; i < 9216; i += 256) {
        int k = i / 96, cc = i - k * 96;
        ws[k * 98 + cc] = g_lwT[k * 192 + cc];
    }
    for (int i = tid; i < 4096; i += 256) cs[(i >> 6) * 65 + (i & 63)] = g_c64[i];
    __syncthreads();
    int ct = tid & 15, rt = tid >> 4;
    int rr0 = rt * 4, cc0 = 2 * ct;
    float2 bv[3];
#pragma unroll
    for (int j = 0; j < 3; j++) bv[j] = *(const float2*)&lb[cc0 + 32 * j];
    float2 acc[4][3];
#pragma unroll
    for (int i = 0; i < 4; i++)
#pragma unroll
        for (int j = 0; j < 3; j++) acc[i][j] = make_float2(0.f, 0.f);
#pragma unroll 4
    for (int k = 0; k < 96; k++) {
        float2 wv[3];
#pragma unroll
        for (int j = 0; j < 3; j++) wv[j] = *(const float2*)&ws[k * 98 + cc0 + 32 * j];
#pragma unroll
        for (int i = 0; i < 4; i++) {
            float x1 = xs[k * 66 + rr0 + i];
            float2 xv = make_float2(x1, x1);
#pragma unroll
            for (int j = 0; j < 3; j++) acc[i][j] = ffma2(xv, wv[j], acc[i][j]);
        }
    }
    __syncthreads();   // xs reads done; reuse region as yx[w*98+c]
#pragma unroll
    for (int i = 0; i < 4; i++)
#pragma unroll
        for (int j = 0; j < 3; j++) {
            float2 v = acc[i][j];
            v.x += bv[j].x; v.y += bv[j].y;
            *(float2*)&xs[(rr0 + i) * 98 + cc0 + 32 * j] = v;
        }
    __syncthreads();
    // DCT along W: out[n][c] = sum_w cs[n][w] * yx[w][c]
    float2 a2[4][3];
#pragma unroll
    for (int i = 0; i < 4; i++)
#pragma unroll
        for (int j = 0; j < 3; j++) a2[i][j] = make_float2(0.f, 0.f);
#pragma unroll 4
    for (int w = 0; w < 64; w++) {
        float2 yv[3];
#pragma unroll
        for (int j = 0; j < 3; j++) yv[j] = *(const float2*)&xs[w * 98 + cc0 + 32 * j];
#pragma unroll
        for (int i = 0; i < 4; i++) {
            float c1 = cs[(rr0 + i) * 65 + w];
            float2 cv = make_float2(c1, c1);
#pragma unroll
            for (int j = 0; j < 3; j++) a2[i][j] = ffma2(cv, yv[j], a2[i][j]);
        }
    }
#pragma unroll
    for (int i = 0; i < 4; i++)
#pragma unroll
        for (int j = 0; j < 3; j++)
            *(float2*)&g_buf1[(r0 + rr0 + i) * 96 + cc0 + 32 * j] = a2[i][j];
}

// ---- linear(z half) + bias + silu: buf0 -> buf2 ----------------------------
__global__ void __launch_bounds__(256) k_linz(const float* __restrict__ lb) {
    extern __shared__ float sm[];
    float* xs = sm;              // 96*66
    float* ws = sm + 6336;       // 96*98
    int tid = threadIdx.x;
    int r0 = blockIdx.x * 64;
    int b = r0 >> 16, thw0 = r0 & 65535;
    for (int i = tid; i < 6144; i += 256) {
        int k = i >> 6, r = i & 63;
        xs[k * 66 + r] = g_buf0[(b * 96 + k) * 65536 + thw0 + r];
    }
    for (int i = tid; i < 9216; i += 256) {
        int k = i / 96, cc = i - k * 96;
        ws[k * 98 + cc] = g_lwT[k * 192 + 96 + cc];
    }
    __syncthreads();
    int ct = tid & 15, rt = tid >> 4;
    int rr0 = rt * 4, cc0 = 2 * ct;
    float2 bv[3];
#pragma unroll
    for (int j = 0; j < 3; j++) bv[j] = *(const float2*)&lb[96 + cc0 + 32 * j];
    float2 acc[4][3];
#pragma unroll
    for (int i = 0; i < 4; i++)
#pragma unroll
        for (int j = 0; j < 3; j++) acc[i][j] = make_float2(0.f, 0.f);
#pragma unroll 4
    for (int k = 0; k < 96; k++) {
        float2 wv[3];
#pragma unroll
        for (int j = 0; j < 3; j++) wv[j] = *(const float2*)&ws[k * 98 + cc0 + 32 * j];
#pragma unroll
        for (int i = 0; i < 4; i++) {
            float x1 = xs[k * 66 + rr0 + i];
            float2 xv = make_float2(x1, x1);
#pragma unroll
            for (int j = 0; j < 3; j++) acc[i][j] = ffma2(xv, wv[j], acc[i][j]);
        }
    }
#pragma unroll
    for (int i = 0; i < 4; i++)
#pragma unroll
        for (int j = 0; j < 3; j++) {
            float2 v = acc[i][j];
            v.x += bv[j].x; v.y += bv[j].y;
            float2 o;
            o.x = v.x / (1.f + expf(-v.x));
            o.y = v.y / (1.f + expf(-v.y));
            *(float2*)&g_buf2[(r0 + rr0 + i) * 96 + cc0 + 32 * j] = o;
        }
}

// ------- tau field: A, B coefficient fields [THW,96] (batch independent) ----
__global__ void __launch_bounds__(256) k_tau(const float* __restrict__ fe,
                                             const float* __restrict__ tb,
                                             const float* __restrict__ cp,
                                             const float* __restrict__ ap) {
    extern __shared__ float sm[];
    float* xs = sm;               // 96*65 = 6240
    float* ws = sm + 6240;        // 96*98 = 9408
    int tid = threadIdx.x;
    int r0 = blockIdx.x * 64;
    for (int i = tid; i < 6144; i += 256) {
        int r = i / 96, k = i - r * 96;
        xs[k * 65 + r] = fe[r0 * 96 + i];
    }
    for (int i = tid; i < 9216; i += 256) {
        int k = i / 96, cc = i - k * 96;
        ws[k * 98 + cc] = g_twT[i];
    }
    __syncthreads();
    float c0 = cp[0], al = ap[0];
    int ct = tid & 15, rt = tid >> 4;
    int rr0 = rt * 4, cc0 = 2 * ct;
    float2 acc[4][3];
#pragma unroll
    for (int i = 0; i < 4; i++)
#pragma unroll
        for (int j = 0; j < 3; j++) acc[i][j] = make_float2(0.f, 0.f);
#pragma unroll 4
    for (int k = 0; k < 96; k++) {
        float2 wv[3];
#pragma unroll
        for (int j = 0; j < 3; j++) wv[j] = *(const float2*)&ws[k * 98 + cc0 + 32 * j];
#pragma unroll
        for (int i = 0; i < 4; i++) {
            float x1 = xs[k * 65 + rr0 + i];
            float2 xv = make_float2(x1, x1);
#pragma unroll
            for (int j = 0; j < 3; j++) acc[i][j] = ffma2(xv, wv[j], acc[i][j]);
        }
    }
#pragma unroll
    for (int i = 0; i < 4; i++) {
#pragma unroll
        for (int j = 0; j < 3; j++) {
            int cc = cc0 + 32 * j;
            float2 v = acc[i][j];
            v.x += tb[cc]; v.y += tb[cc + 1];
            float2 Av, Bv;
            {
                float g = 0.5f * v.x * (1.f + erff(v.x * 0.70710678118654752f));
                float si, co; sincosf(c0 * g, &si, &co);
                float damp = expf(-0.5f * al * g);
                float so = si / (c0 + 1e-8f);
                Av.x = damp * (co + so * al * 0.5f); Bv.x = damp * so;
            }
            {
                float g = 0.5f * v.y * (1.f + erff(v.y * 0.70710678118654752f));
                float si, co; sincosf(c0 * g, &si, &co);
                float damp = expf(-0.5f * al * g);
                float so = si / (c0 + 1e-8f);
                Av.y = damp * (co + so * al * 0.5f); Bv.y = damp * so;
            }
            int idx = (r0 + rr0 + i) * 96 + cc;
            *(float2*)&g_A[idx]  = Av;
            *(float2*)&g_Bc[idx] = Bv;
        }
    }
}

// ---------- 64-pt transform along H axis: out = M @ in ----------------------
__global__ void __launch_bounds__(256) k_dctH(const float* __restrict__ in,
                                              float* __restrict__ out,
                                              const float* __restrict__ M) {
    __shared__ float cs[64 * 65];
    __shared__ float xs[64 * 98];
    int tid = threadIdx.x;
    for (int i = tid; i < 4096; i += 256) cs[(i >> 6) * 65 + (i & 63)] = M[i];
    int slab = blockIdx.x;
    int outer = slab >> 6, inner = slab & 63;   // outer: b*16+t, inner: w
    int base = outer * TSTR + inner * 96;
    for (int i = tid; i < 3072; i += 256) {
        int k = i / 48, c2 = i - k * 48;
        float2 v = *(const float2*)&in[base + k * 6144 + c2 * 2];
        *(float2*)&xs[k * 98 + c2 * 2] = v;
    }
    __syncthreads();
    int ct = tid & 15, rt = tid >> 4;
    int n0 = rt * 4, cc0 = 2 * ct;
    float2 acc[4][3];
#pragma unroll
    for (int i = 0; i < 4; i++)
#pragma unroll
        for (int j = 0; j < 3; j++) acc[i][j] = make_float2(0.f, 0.f);
#pragma unroll 4
    for (int k = 0; k < 64; k++) {
        float2 xv[3];
#pragma unroll
        for (int j = 0; j < 3; j++) xv[j] = *(const float2*)&xs[k * 98 + cc0 + 32 * j];
#pragma unroll
        for (int i = 0; i < 4; i++) {
            float c1 = cs[(n0 + i) * 65 + k];
            float2 cv = make_float2(c1, c1);
#pragma unroll
            for (int j = 0; j < 3; j++) acc[i][j] = ffma2(cv, xv[j], acc[i][j]);
        }
    }
#pragma unroll
    for (int i = 0; i < 4; i++)
#pragma unroll
        for (int j = 0; j < 3; j++)
            *(float2*)&out[base + (n0 + i) * 6144 + cc0 + 32 * j] = acc[i][j];
}

// ---- fused: DCT_T + v0 channel-mix + spectral combine + IDCT_T per slab ----
__global__ void __launch_bounds__(256) k_fusedT(const float* __restrict__ in,
                                                float* __restrict__ out,
                                                const float* __restrict__ vb) {
    extern __shared__ float sm[];
    float* wsm  = sm;            // 96*98 = 9408
    float* x16  = sm + 9408;     // 1536
    float* u0   = x16 + 1536;    // 1536
    float* vs   = u0 + 1536;     // 1536
    float* c16s = vs + 1536;     // 256
    float* c16t = c16s + 256;    // 256
    int tid = threadIdx.x;
    int b = blockIdx.x >> 12, hw = blockIdx.x & 4095;
    int base = b * BSTR + hw * 96;
    for (int i = tid; i < 9216; i += 256) {
        int k = i / 96, cc = i - k * 96;
        wsm[k * 98 + cc] = g_vwT[i];
    }
    c16s[tid] = g_c16[tid];
    c16t[tid] = g_c16T[tid];
    for (int i = tid; i < 1536; i += 256) {
        int t = i / 96, c = i - t * 96;
        x16[i] = in[base + t * TSTR + c];
    }
    __syncthreads();
    int ct = tid & 15, nt = tid >> 4;
    int cc0 = 2 * ct;
    // hoist spectral coefficient loads (coalesced 128B lines per warp)
    float2 Av[3], Bv[3];
#pragma unroll
    for (int j = 0; j < 3; j++) {
        int gi = (nt * 4096 + hw) * 96 + cc0 + 32 * j;
        Av[j] = *(const float2*)&g_A[gi];
        Bv[j] = *(const float2*)&g_Bc[gi];
    }
    // forward DCT along T (thread owns frequency row n = nt, 6 channels)
    {
        float2 a[3] = {make_float2(0,0), make_float2(0,0), make_float2(0,0)};
#pragma unroll
        for (int t = 0; t < 16; t++) {
            float c1 = c16s[nt * 16 + t];
            float2 cv = make_float2(c1, c1);
#pragma unroll
            for (int j = 0; j < 3; j++)
                a[j] = ffma2(cv, *(const float2*)&x16[t * 96 + cc0 + 32 * j], a[j]);
        }
#pragma unroll
        for (int j = 0; j < 3; j++) *(float2*)&u0[nt * 96 + cc0 + 32 * j] = a[j];
    }
    __syncthreads();
    // v0 mix (freq domain) + spectral combine -> vs
    {
        float2 v[3] = {make_float2(0,0), make_float2(0,0), make_float2(0,0)};
#pragma unroll 4
        for (int k = 0; k < 96; k++) {
            float u1 = u0[nt * 96 + k];
            float2 uv = make_float2(u1, u1);
#pragma unroll
            for (int j = 0; j < 3; j++)
                v[j] = ffma2(uv, *(const float2*)&wsm[k * 98 + cc0 + 32 * j], v[j]);
        }
        if (hw == 0 && nt == 0) {  // DC of constant v0_b field: 256*v0_b
#pragma unroll
            for (int j = 0; j < 3; j++) {
                v[j].x += 256.f * vb[cc0 + 32 * j];
                v[j].y += 256.f * vb[cc0 + 32 * j + 1];
            }
        }
#pragma unroll
        for (int j = 0; j < 3; j++) {
            float2 uu = *(const float2*)&u0[nt * 96 + cc0 + 32 * j];
            float2 r;
            r.x = Av[j].x * uu.x + Bv[j].x * v[j].x;
            r.y = Av[j].y * uu.y + Bv[j].y * v[j].y;
            *(float2*)&vs[nt * 96 + cc0 + 32 * j] = r;
        }
    }
    __syncthreads();
    // inverse DCT along T (thread owns time index t = nt)
    {
        float2 y[3] = {make_float2(0,0), make_float2(0,0), make_float2(0,0)};
#pragma unroll
        for (int n = 0; n < 16; n++) {
            float c1 = c16t[nt * 16 + n];
            float2 cv = make_float2(c1, c1);
#pragma unroll
            for (int j = 0; j < 3; j++)
                y[j] = ffma2(cv, *(const float2*)&vs[n * 96 + cc0 + 32 * j], y[j]);
        }
#pragma unroll
        for (int j = 0; j < 3; j++)
            *(float2*)&out[base + nt * TSTR + cc0 + 32 * j] = y[j];
    }
}

// ---- final: IDCT_W + LayerNorm + gate + out GEMM + transpose store ---------
__global__ void __launch_bounds__(256) k_final(const float* __restrict__ lg,
                                               const float* __restrict__ lbt,
                                               const float* __restrict__ ob,
                                               float* __restrict__ outp) {
    extern __shared__ float sm[];
    float* s  = sm;              // 64*98 = 6272 (freq slab, then spatial, then LN'd)
    float* cs = sm + 6272;       // 64*65 = 4160
    float* ws = cs + 4160;       // 96*98 = 9408
    float* os = ws + 9408;       // 96*66 = 6336
    int tid = threadIdx.x;
    int r0 = blockIdx.x * 64;
    int b = r0 >> 16, thw0 = r0 & 65535;
    for (int i = tid; i < 6144; i += 256) {
        int n = i / 96, c = i - n * 96;
        s[n * 98 + c] = g_buf3[r0 * 96 + i];
    }
    for (int i = tid; i < 4096; i += 256) cs[(i >> 6) * 65 + (i & 63)] = g_c64T[i];
    for (int i = tid; i < 9216; i += 256) {
        int k = i / 96, cc = i - k * 96;
        ws[k * 98 + cc] = g_owT[i];
    }
    __syncthreads();
    int ct = tid & 15, rt = tid >> 4;
    int rr0 = rt * 4, cc0 = 2 * ct;
    // IDCT along W: x[w][c] = sum_n cs[w][n] * s[n][c]
    float2 xw[4][3];
#pragma unroll
    for (int i = 0; i < 4; i++)
#pragma unroll
        for (int j = 0; j < 3; j++) xw[i][j] = make_float2(0.f, 0.f);
#pragma unroll 4
    for (int n = 0; n < 64; n++) {
        float2 sv[3];
#pragma unroll
        for (int j = 0; j < 3; j++) sv[j] = *(const float2*)&s[n * 98 + cc0 + 32 * j];
#pragma unroll
        for (int i = 0; i < 4; i++) {
            float c1 = cs[(rr0 + i) * 65 + n];
            float2 cv = make_float2(c1, c1);
#pragma unroll
            for (int j = 0; j < 3; j++) xw[i][j] = ffma2(cv, sv[j], xw[i][j]);
        }
    }
    __syncthreads();
#pragma unroll
    for (int i = 0; i < 4; i++)
#pragma unroll
        for (int j = 0; j < 3; j++)
            *(float2*)&s[(rr0 + i) * 98 + cc0 + 32 * j] = xw[i][j];
    __syncthreads();
    // LayerNorm + gate; warp handles 8 rows, lane covers cols {lane, lane+32, lane+64}
    {
        int wp = tid >> 5, lane = tid & 31;
        float g0 = lg[lane], g1 = lg[lane + 32], g2 = lg[lane + 64];
        float b0 = lbt[lane], b1 = lbt[lane + 32], b2 = lbt[lane + 64];
#pragma unroll
        for (int rr = 0; rr < 8; rr++) {
            int w = wp * 8 + rr;
            float x0 = s[w * 98 + lane], x1 = s[w * 98 + lane + 32], x2 = s[w * 98 + lane + 64];
            float sum = x0 + x1 + x2, q = x0 * x0 + x1 * x1 + x2 * x2;
#pragma unroll
            for (int o = 16; o > 0; o >>= 1) {
                sum += __shfl_xor_sync(0xffffffffu, sum, o);
                q   += __shfl_xor_sync(0xffffffffu, q, o);
            }
            float mean = sum * (1.f / 96.f);
            float var = q * (1.f / 96.f) - mean * mean;
            float rstd = rsqrtf(var + 1e-5f);
            int gr = (r0 + w) * 96;
            s[w * 98 + lane]      = ((x0 - mean) * rstd * g0 + b0) * g_buf2[gr + lane];
            s[w * 98 + lane + 32] = ((x1 - mean) * rstd * g1 + b1) * g_buf2[gr + lane + 32];
            s[w * 98 + lane + 64] = ((x2 - mean) * rstd * g2 + b2) * g_buf2[gr + lane + 64];
        }
    }
    __syncthreads();
    // out GEMM: os[cc][w] = sum_k s[w][k] * ws[k][cc] + ob
    float2 acc[4][3];
#pragma unroll
    for (int i = 0; i < 4; i++)
#pragma unroll
        for (int j = 0; j < 3; j++) acc[i][j] = make_float2(0.f, 0.f);
#pragma unroll 4
    for (int k = 0; k < 96; k++) {
        float2 wv[3];
#pragma unroll
        for (int j = 0; j < 3; j++) wv[j] = *(const float2*)&ws[k * 98 + cc0 + 32 * j];
#pragma unroll
        for (int i = 0; i < 4; i++) {
            float x1 = s[(rr0 + i) * 98 + k];
            float2 xv = make_float2(x1, x1);
#pragma unroll
            for (int j = 0; j < 3; j++) acc[i][j] = ffma2(xv, wv[j], acc[i][j]);
        }
    }
#pragma unroll
    for (int i = 0; i < 4; i++)
#pragma unroll
        for (int j = 0; j < 3; j++) {
            int cc = cc0 + 32 * j;
            os[cc * 66 + rr0 + i]       = acc[i][j].x + ob[cc];
            os[(cc + 1) * 66 + rr0 + i] = acc[i][j].y + ob[cc + 1];
        }
    __syncthreads();
    for (int i = tid; i < 6144; i += 256) {
        int cc = i >> 6, w = i & 63;
        outp[b * BSTR + cc * 65536 + thw0 + w] = os[cc * 66 + w];
    }
}

extern "C" void kernel_launch(void* const* d_in, const int* in_sizes, int n_in,
                              void* d_out, int out_size) {
    const float* x   = (const float*)d_in[0];
    const float* fe  = (const float*)d_in[1];
    const float* dww = (const float*)d_in[2];
    const float* dwb = (const float*)d_in[3];
    const float* lw  = (const float*)d_in[4];
    const float* lb  = (const float*)d_in[5];
    const float* vw  = (const float*)d_in[6];
    const float* vb  = (const float*)d_in[7];
    const float* tw  = (const float*)d_in[8];
    const float* tb  = (const float*)d_in[9];
    const float* cc  = (const float*)d_in[10];
    const float* al  = (const float*)d_in[11];
    const float* lg  = (const float*)d_in[12];
    const float* lbt = (const float*)d_in[13];
    const float* ow  = (const float*)d_in[14];
    const float* ob  = (const float*)d_in[15];
    float* outp = (float*)d_out;

    size_t smXG  = (size_t)(6336 + 9408 + 4160) * 4;  // 79616
    size_t smZ   = (size_t)(6336 + 9408) * 4;         // 62976
    size_t smTau = (size_t)(6240 + 9408) * 4;         // 62592
    size_t smFus = (size_t)(9408 + 3 * 1536 + 512) * 4; // 58112
    size_t smFin = (size_t)(6272 + 4160 + 9408 + 6336) * 4; // 104704
    cudaFuncSetAttribute(k_linxg, cudaFuncAttributeMaxDynamicSharedMemorySize, (int)smXG);
    cudaFuncSetAttribute(k_linz,  cudaFuncAttributeMaxDynamicSharedMemorySize, (int)smZ);
    cudaFuncSetAttribute(k_tau,   cudaFuncAttributeMaxDynamicSharedMemorySize, (int)smTau);
    cudaFuncSetAttribute(k_fusedT, cudaFuncAttributeMaxDynamicSharedMemorySize, (int)smFus);
    cudaFuncSetAttribute(k_final, cudaFuncAttributeMaxDynamicSharedMemorySize, (int)smFin);

    float *b1, *b3, *c64, *c64T;
    cudaGetSymbolAddress((void**)&b1, g_buf1);
    cudaGetSymbolAddress((void**)&b3, g_buf3);
    cudaGetSymbolAddress((void**)&c64, g_c64);
    cudaGetSymbolAddress((void**)&c64T, g_c64T);

    k_cosinit<<<1, 256>>>();
    k_prepw<<<180, 256>>>(lw, tw, vw, ow);
    k_conv<<<dim3(2, 16, 192), 256>>>(x, dww, dwb);
    k_linxg<<<2048, 256, smXG>>>(lb);                 // linear(xg) + DCT_W -> buf1
    k_linz<<<2048, 256, smZ>>>(lb);                   // linear(z) + silu -> buf2
    k_tau<<<1024, 256, smTau>>>(fe, tb, cc, al);
    k_dctH<<<2048, 256>>>(b1, b3, c64);               // DCT along H -> buf3
    k_fusedT<<<8192, 256, smFus>>>(b3, b1, vb);       // DCT_T + mix + IDCT_T -> buf1
    k_dctH<<<2048, 256>>>(b1, b3, c64T);              // IDCT along H -> buf3
    k_final<<<2048, 256, smFin>>>(lg, lbt, ob, outp); // IDCT_W + LN + gate + GEMM
}